// round 6
// baseline (speedup 1.0000x reference)
#include <cuda_runtime.h>
#include <cuda_bf16.h>

typedef unsigned long long ull;
typedef unsigned char uchar;

#define NB 8
#define TQ 1000
#define TKDIM 256

// scratch (device globals; no allocation allowed)
__device__ float g_H1[NB * 1024 * TKDIM];   // key hidden  (8 MB)
__device__ float g_keys[NB * 80 * TKDIM];   // keys        (0.65 MB)
__device__ float g_H2[NB * 160 * TQ];       // query hidden(5.1 MB)
__device__ float g_Q[NB * 80 * TQ];         // queries     (2.56 MB)
__device__ int   g_maskmode;                // 0=u8, 1=i32, 2=f32

__device__ __forceinline__ void fma2(ull& d, ull a, ull b) {
    asm("fma.rn.f32x2 %0, %1, %2, %0;" : "+l"(d) : "l"(a), "l"(b));
}
__device__ __forceinline__ ull pack2(float x) {
    ull r; asm("mov.b64 %0, {%1, %1};" : "=l"(r) : "f"(x)); return r;
}
__device__ __forceinline__ float2 unpack2(ull v) {
    float2 r; asm("mov.b64 {%0, %1}, %2;" : "=f"(r.x), "=f"(r.y) : "l"(v)); return r;
}

// ---------------------------------------------------------------------------
// Mask dtype detector: inspects first 1024 bytes (safe: buffer >= 2,048,000 B
// under every hypothesis). bool-as-int32 -> dwords in {0,1};
// bool-as-float32 -> dwords in {0, 0x3F800000}; bool-as-uint8 -> e.g. 0x01010101.
// ---------------------------------------------------------------------------
__global__ void detect_mask_kernel(const uchar* __restrict__ mask)
{
    if (threadIdx.x == 0) {
        const unsigned* d = (const unsigned*)mask;
        bool i32 = true, f32 = true;
        for (int i = 0; i < 256; i++) {
            unsigned v = d[i];
            if (v != 0u && v != 1u) i32 = false;
            if (v != 0u && v != 0x3F800000u) f32 = false;
        }
        g_maskmode = i32 ? 1 : (f32 ? 2 : 0);
    }
}

// ---------------------------------------------------------------------------
// Generic conv-as-GEMM: Y[b, m, t] = bias[m] + sum_{ci,k} W[m, ci*KW+k] * X[b, ci, t+k-halo]
// ---------------------------------------------------------------------------
template <int TM, int TN, int MM, int MN, int KW, bool RELU>
__global__ void __launch_bounds__(256) convgemm_kernel(
    const float* __restrict__ W, const float* __restrict__ bias,
    const float* __restrict__ X, float* __restrict__ Y,
    int M, int T, int Cin)
{
    static_assert(TN == 128, "B-load indexing assumes TN=128");
    constexpr int TK = 16;
    constexpr int ASTR = TM + 4;
    __shared__ float As[TK * ASTR];
    __shared__ float Bs[TK * TN];

    const int K = Cin * KW;
    const int b  = blockIdx.z;
    const int m0 = blockIdx.y * TM;
    const int t0 = blockIdx.x * TN;
    const int tid = threadIdx.x;
    const int tx = tid & 15;
    const int ty = tid >> 4;
    const float* Xb = X + (long)b * Cin * T;
    constexpr int HALO = KW >> 1;

    ull acc[MM][MN / 2];
#pragma unroll
    for (int i = 0; i < MM; i++)
#pragma unroll
        for (int j = 0; j < MN / 2; j++) acc[i][j] = 0ull;

    for (int k0 = 0; k0 < K; k0 += TK) {
#pragma unroll
        for (int i = 0; i < (TK * TM) / 256; i++) {
            int idx = tid + 256 * i;
            int kk = idx & (TK - 1);
            int m  = idx >> 4;
            int gm = m0 + m;
            As[kk * ASTR + m] = (gm < M) ? W[(long)gm * K + k0 + kk] : 0.f;
        }
#pragma unroll
        for (int i = 0; i < (TK * TN) / 256; i++) {
            int idx = tid + 256 * i;
            int tl = idx & (TN - 1);
            int kk = idx >> 7;
            int gk = k0 + kk;
            int ci = gk / KW;
            int kw = gk - ci * KW;
            int src = t0 + tl + kw - HALO;
            Bs[kk * TN + tl] = (src >= 0 && src < T) ? Xb[(long)ci * T + src] : 0.f;
        }
        __syncthreads();
#pragma unroll
        for (int kk = 0; kk < TK; kk++) {
            float a[MM];
            const float4* ap = (const float4*)&As[kk * ASTR + ty * MM];
            *(float4*)&a[0] = ap[0];
            if constexpr (MM == 8) *(float4*)&a[4] = ap[1];
            ull bv[MN / 2];
            const longlong2* bp = (const longlong2*)&Bs[kk * TN + tx * MN];
            { longlong2 q0 = bp[0]; bv[0] = (ull)q0.x; bv[1] = (ull)q0.y; }
            if constexpr (MN == 8) {
                longlong2 q1 = bp[1]; bv[2] = (ull)q1.x; bv[3] = (ull)q1.y;
            }
#pragma unroll
            for (int i = 0; i < MM; i++) {
                ull ad = pack2(a[i]);
#pragma unroll
                for (int j = 0; j < MN / 2; j++) fma2(acc[i][j], ad, bv[j]);
            }
        }
        __syncthreads();
    }

#pragma unroll
    for (int i = 0; i < MM; i++) {
        int gm = m0 + ty * MM + i;
        if (gm >= M) continue;
        float bb = bias[gm];
        float* Yr = Y + ((long)b * M + gm) * T;
#pragma unroll
        for (int j = 0; j < MN / 2; j++) {
            float2 v = unpack2(acc[i][j]);
            v.x += bb; v.y += bb;
            if (RELU) { v.x = fmaxf(v.x, 0.f); v.y = fmaxf(v.y, 0.f); }
            int gt = t0 + tx * MN + 2 * j;
            if (gt < T) Yr[gt] = v.x;
            if (gt + 1 < T) Yr[gt + 1] = v.y;
        }
    }
}

// ---------------------------------------------------------------------------
// kconv2: keys[b, m, t] = kb2[m] + sum_c kw2[m, c] * H1[b, c, t]
// ---------------------------------------------------------------------------
__global__ void __launch_bounds__(256) kconv2_kernel(
    const float* __restrict__ W2, const float* __restrict__ bias)
{
    __shared__ float hs[64 * 16];
    __shared__ float ws[80 * 64];
    const int b  = blockIdx.y;
    const int t0 = blockIdx.x * 16;
    const int tx = threadIdx.x;
    const int ty = threadIdx.y;
    const int tid = ty * 16 + tx;
    float acc[5] = {0.f, 0.f, 0.f, 0.f, 0.f};
    const float* H1b = g_H1 + (long)b * 1024 * 256;

    for (int c0 = 0; c0 < 1024; c0 += 64) {
#pragma unroll
        for (int i = 0; i < 4; i++) {
            int idx = tid + 256 * i;
            int t = idx & 15, c = idx >> 4;
            hs[c * 16 + t] = H1b[(long)(c0 + c) * 256 + t0 + t];
        }
#pragma unroll
        for (int i = 0; i < 20; i++) {
            int idx = tid + 256 * i;
            int cl = idx & 63, m = idx >> 6;
            ws[m * 64 + cl] = W2[(long)m * 1024 + c0 + cl];
        }
        __syncthreads();
#pragma unroll 8
        for (int cl = 0; cl < 64; cl++) {
            float hv = hs[cl * 16 + tx];
#pragma unroll
            for (int j = 0; j < 5; j++) acc[j] += ws[(ty + 16 * j) * 64 + cl] * hv;
        }
        __syncthreads();
    }
#pragma unroll
    for (int j = 0; j < 5; j++) {
        int m = ty + 16 * j;
        g_keys[((long)b * 80 + m) * 256 + t0 + tx] = acc[j] + bias[m];
    }
}

// ---------------------------------------------------------------------------
// qconv2 + relu + qconv3 fused
// ---------------------------------------------------------------------------
__global__ void __launch_bounds__(256) qconv23_kernel(
    const float* __restrict__ W2, const float* __restrict__ b2,
    const float* __restrict__ W3, const float* __restrict__ b3)
{
    __shared__ float pool[2560 + 5120 + 2560];
    float* h3s = pool;            // 80*32
    float* h2s = pool + 2560;     // 160*32
    float* w2t = pool + 7680;     // 80*32
    float* w3s = pool + 2560;     // 80*80 (phase 2)

    const int b  = blockIdx.y;
    const int t0 = blockIdx.x * 32;
    const int tx = threadIdx.x;
    const int ty = threadIdx.y;
    const int tid = ty * 32 + tx;
    const float* H2b = g_H2 + (long)b * 160 * 1000;

#pragma unroll
    for (int i = 0; i < 20; i++) {
        int idx = tid + 256 * i;
        int t = idx & 31, c = idx >> 5;
        int gt = t0 + t;
        h2s[c * 32 + t] = (gt < 1000) ? H2b[(long)c * 1000 + gt] : 0.f;
    }

    float acc[10];
#pragma unroll
    for (int j = 0; j < 10; j++) acc[j] = 0.f;

    for (int ct = 0; ct < 5; ct++) {
        __syncthreads();
#pragma unroll
        for (int i = 0; i < 10; i++) {
            int idx = tid + 256 * i;
            int cl = idx & 31, m = idx >> 5;
            w2t[m * 32 + cl] = W2[m * 160 + ct * 32 + cl];
        }
        __syncthreads();
#pragma unroll 4
        for (int cl = 0; cl < 32; cl++) {
            float hv = h2s[(ct * 32 + cl) * 32 + tx];
#pragma unroll
            for (int j = 0; j < 10; j++) acc[j] += w2t[(ty + 8 * j) * 32 + cl] * hv;
        }
    }
    __syncthreads();
#pragma unroll
    for (int j = 0; j < 10; j++) {
        int m = ty + 8 * j;
        h3s[m * 32 + tx] = fmaxf(acc[j] + b2[m], 0.f);
    }
    __syncthreads();
#pragma unroll
    for (int i = 0; i < 25; i++) {
        int idx = tid + 256 * i;
        w3s[idx] = W3[idx];
    }
    __syncthreads();

    float acc2[10];
#pragma unroll
    for (int j = 0; j < 10; j++) acc2[j] = 0.f;
#pragma unroll 4
    for (int c = 0; c < 80; c++) {
        float hv = h3s[c * 32 + tx];
#pragma unroll
        for (int j = 0; j < 10; j++) acc2[j] += w3s[(ty + 8 * j) * 80 + c] * hv;
    }
    int gt = t0 + tx;
    if (gt < 1000) {
#pragma unroll
        for (int j = 0; j < 10; j++) {
            int m = ty + 8 * j;
            g_Q[((long)b * 80 + m) * 1000 + gt] = acc2[j] + b3[m];
        }
    }
}

// ---------------------------------------------------------------------------
// attention: out = log_softmax(-T*|q-k|^2) + log(prior+1e-8); !mask -> -inf.
// q^2 cancels in log_softmax -> s_j = T*(2 q.k_j - |k_j|^2).
// ---------------------------------------------------------------------------
__global__ void __launch_bounds__(256) attn_kernel(
    const float* __restrict__ prior, const void* __restrict__ maskraw,
    float* __restrict__ out)
{
    __shared__ __nv_bfloat16 ks[80 * 256];
    __shared__ float k2s[256];
    __shared__ float qs[8 * 80];

    const int b = blockIdx.y;
    const int tid = threadIdx.x;
    const int mode = g_maskmode;
    const float* keysb = g_keys + (long)b * 80 * 256;

    for (int idx = tid; idx < 80 * 256; idx += 256)
        ks[idx] = __float2bfloat16(keysb[idx]);
    __syncthreads();
    {
        int t = tid;
        float s = 0.f;
#pragma unroll 8
        for (int c = 0; c < 80; c++) {
            float v = __bfloat162float(ks[c * 256 + t]);
            s += v * v;
        }
        k2s[t] = s;
    }
    __syncthreads();

    const int wid = tid >> 5, lane = tid & 31;
    for (int it = 0; it < 5; it++) {
        int row = blockIdx.x * 40 + it * 8 + wid;
        for (int c = lane; c < 80; c += 32)
            qs[wid * 80 + c] = g_Q[((long)b * 80 + c) * 1000 + row];
        __syncwarp();

        float acc[8];
#pragma unroll
        for (int j = 0; j < 8; j++) acc[j] = 0.f;
#pragma unroll 4
        for (int c = 0; c < 80; c++) {
            float qv = qs[wid * 80 + c];
            uint4 kv = *(const uint4*)&ks[c * 256 + lane * 8];
            float2 f0 = __bfloat1622float2(*(__nv_bfloat162*)&kv.x);
            float2 f1 = __bfloat1622float2(*(__nv_bfloat162*)&kv.y);
            float2 f2 = __bfloat1622float2(*(__nv_bfloat162*)&kv.z);
            float2 f3 = __bfloat1622float2(*(__nv_bfloat162*)&kv.w);
            acc[0] += qv * f0.x; acc[1] += qv * f0.y;
            acc[2] += qv * f1.x; acc[3] += qv * f1.y;
            acc[4] += qv * f2.x; acc[5] += qv * f2.y;
            acc[6] += qv * f3.x; acc[7] += qv * f3.y;
        }

        float s[8];
        float mx = -1e30f;
#pragma unroll
        for (int j = 0; j < 8; j++) {
            s[j] = 0.0005f * (2.f * acc[j] - k2s[lane * 8 + j]);
            mx = fmaxf(mx, s[j]);
        }
#pragma unroll
        for (int o = 16; o > 0; o >>= 1) mx = fmaxf(mx, __shfl_xor_sync(0xffffffffu, mx, o));
        float sum = 0.f;
#pragma unroll
        for (int j = 0; j < 8; j++) sum += __expf(s[j] - mx);
#pragma unroll
        for (int o = 16; o > 0; o >>= 1) sum += __shfl_xor_sync(0xffffffffu, sum, o);
        float lse = mx + __logf(sum);

        long base = ((long)(b * 1000 + row)) * 256 + lane * 8;
        float4 p0 = *(const float4*)(prior + base);
        float4 p1 = *(const float4*)(prior + base + 4);
        const float NEG = __int_as_float(0xff800000);
        float o8[8];
        o8[0] = s[0] - lse + __logf(p0.x + 1e-8f);
        o8[1] = s[1] - lse + __logf(p0.y + 1e-8f);
        o8[2] = s[2] - lse + __logf(p0.z + 1e-8f);
        o8[3] = s[3] - lse + __logf(p0.w + 1e-8f);
        o8[4] = s[4] - lse + __logf(p1.x + 1e-8f);
        o8[5] = s[5] - lse + __logf(p1.y + 1e-8f);
        o8[6] = s[6] - lse + __logf(p1.z + 1e-8f);
        o8[7] = s[7] - lse + __logf(p1.w + 1e-8f);

        if (mode == 1) {
            const int* mp = (const int*)maskraw;
#pragma unroll
            for (int j = 0; j < 8; j++) if (mp[base + j] == 0) o8[j] = NEG;
        } else if (mode == 2) {
            const float* mp = (const float*)maskraw;
#pragma unroll
            for (int j = 0; j < 8; j++) if (mp[base + j] == 0.f) o8[j] = NEG;
        } else {
            const uchar* mp = (const uchar*)maskraw;
            uchar4 m0 = *(const uchar4*)(mp + base);
            uchar4 m1 = *(const uchar4*)(mp + base + 4);
            if (!m0.x) o8[0] = NEG; if (!m0.y) o8[1] = NEG;
            if (!m0.z) o8[2] = NEG; if (!m0.w) o8[3] = NEG;
            if (!m1.x) o8[4] = NEG; if (!m1.y) o8[5] = NEG;
            if (!m1.z) o8[6] = NEG; if (!m1.w) o8[7] = NEG;
        }

        *(float4*)(out + base)     = make_float4(o8[0], o8[1], o8[2], o8[3]);
        *(float4*)(out + base + 4) = make_float4(o8[4], o8[5], o8[6], o8[7]);
        __syncwarp();
    }
}

// ---------------------------------------------------------------------------
extern "C" void kernel_launch(void* const* d_in, const int* in_sizes, int n_in,
                              void* d_out, int out_size)
{
    const float* phonemes = (const float*)d_in[0];
    const float* audio    = (const float*)d_in[1];
    const uchar* mask     = (const uchar*)d_in[2];
    const float* prior    = (const float*)d_in[3];
    const float* kw1 = (const float*)d_in[4];
    const float* kb1 = (const float*)d_in[5];
    const float* kw2 = (const float*)d_in[6];
    const float* kb2 = (const float*)d_in[7];
    const float* qw1 = (const float*)d_in[8];
    const float* qb1 = (const float*)d_in[9];
    const float* qw2 = (const float*)d_in[10];
    const float* qb2 = (const float*)d_in[11];
    const float* qw3 = (const float*)d_in[12];
    const float* qb3 = (const float*)d_in[13];
    float* out = (float*)d_out;

    void* p;
    cudaGetSymbolAddress(&p, g_H1);  float* H1 = (float*)p;
    cudaGetSymbolAddress(&p, g_H2);  float* H2 = (float*)p;

    detect_mask_kernel<<<1, 32>>>(mask);
    // key path: conv(512->1024,k3)+relu  -> H1
    convgemm_kernel<128, 128, 8, 8, 3, true><<<dim3(2, 8, 8), 256>>>(
        kw1, kb1, phonemes, H1, 1024, 256, 512);
    // query path: conv(80->160,k3)+relu -> H2
    convgemm_kernel<64, 128, 4, 8, 3, true><<<dim3(8, 3, 8), 256>>>(
        qw1, qb1, audio, H2, 160, 1000, 80);
    // keys = conv1x1(H1, 1024->80) + bias
    kconv2_kernel<<<dim3(16, 8), dim3(16, 16)>>>(kw2, kb2);
    // queries = conv1x1(relu(conv1x1(H2,160->80)),80->80)
    qconv23_kernel<<<dim3(32, 8), dim3(32, 8)>>>(qw2, qb2, qw3, qb3);
    // attention + log_softmax + prior + mask
    attn_kernel<<<dim3(25, 8), 256>>>(prior, mask, out);
}

// round 7
// speedup vs baseline: 1.9968x; 1.9968x over previous
#include <cuda_runtime.h>
#include <cuda_bf16.h>
#include <cstdint>

typedef unsigned char uchar;
typedef __nv_bfloat16 bf16;

#define NB 8

// ---------------- device scratch (zero-initialized at module load) ----------
__device__ bf16 g_wk1[1024 * 1536];
__device__ bf16 g_wq1[160 * 240];
__device__ bf16 g_wk2[80 * 1024];
__device__ bf16 g_wq2[80 * 160];
__device__ bf16 g_wq3[80 * 80];
__device__ bf16 g_phon [NB * 512 * 264];     // padded (halo 1, stride 264)
__device__ bf16 g_audio[NB * 80 * 1032];     // padded (halo 1, stride 1032)
__device__ bf16 g_H1b[NB * 1024 * 256];
__device__ bf16 g_H2b[NB * 160 * 1000 + 64]; // +slack for harmless tile overread
__device__ bf16 g_H3b[NB * 80 * 1000 + 64];
__device__ float g_keys[NB * 80 * 256];
__device__ float g_Q[NB * 80 * 1000];
__device__ int   g_maskmode;                 // 0=u8, 1=i32, 2=f32

// ---------------- mask dtype detector --------------------------------------
__global__ void detect_mask_kernel(const uchar* __restrict__ mask)
{
    if (threadIdx.x == 0) {
        const unsigned* d = (const unsigned*)mask;
        bool i32 = true, f32 = true;
        for (int i = 0; i < 256; i++) {
            unsigned v = d[i];
            if (v != 0u && v != 1u) i32 = false;
            if (v != 0u && v != 0x3F800000u) f32 = false;
        }
        g_maskmode = i32 ? 1 : (f32 ? 2 : 0);
    }
}

// ---------------- one-shot conversions --------------------------------------
__global__ void prep_weights_kernel(
    const float* __restrict__ kw1, const float* __restrict__ qw1,
    const float* __restrict__ kw2, const float* __restrict__ qw2,
    const float* __restrict__ qw3)
{
    const int N1 = 1024 * 1536, N2 = 160 * 240, N3 = 80 * 1024,
              N4 = 80 * 160, N5 = 80 * 80;
    long i = (long)blockIdx.x * blockDim.x + threadIdx.x;
    long total = N1 + N2 + N3 + N4 + N5;
    if (i >= total) return;
    if (i < N1) { g_wk1[i] = __float2bfloat16(kw1[i]); return; }
    i -= N1;
    if (i < N2) { g_wq1[i] = __float2bfloat16(qw1[i]); return; }
    i -= N2;
    if (i < N3) { g_wk2[i] = __float2bfloat16(kw2[i]); return; }
    i -= N3;
    if (i < N4) { g_wq2[i] = __float2bfloat16(qw2[i]); return; }
    i -= N4;
    g_wq3[i] = __float2bfloat16(qw3[i]);
}

__global__ void prep_inputs_kernel(
    const float* __restrict__ phonemes, const float* __restrict__ audio)
{
    // region 1: phonemes  rows=NB*512, T=256, XS=264, halo=1
    // region 2: audio     rows=NB*80,  T=1000, XS=1032, halo=1
    const long NP = (long)NB * 512 * 264;
    const long NA = (long)NB * 80 * 1032;
    long i = (long)blockIdx.x * blockDim.x + threadIdx.x;
    if (i < NP) {
        long r = i / 264; int x = (int)(i - r * 264);
        bf16 v = __float2bfloat16(0.f);
        if (x >= 1 && x <= 256) v = __float2bfloat16(phonemes[r * 256 + x - 1]);
        g_phon[i] = v;
        return;
    }
    i -= NP;
    if (i < NA) {
        long r = i / 1032; int x = (int)(i - r * 1032);
        bf16 v = __float2bfloat16(0.f);
        if (x >= 1 && x <= 1000) v = __float2bfloat16(audio[r * 1000 + x - 1]);
        g_audio[i] = v;
    }
}

// ---------------- mma helpers ------------------------------------------------
__device__ __forceinline__ uint32_t smem_u32(const void* p) {
    return (uint32_t)__cvta_generic_to_shared(p);
}
__device__ __forceinline__ void ldsm4(uint32_t& r0, uint32_t& r1,
                                      uint32_t& r2, uint32_t& r3, uint32_t a) {
    asm volatile("ldmatrix.sync.aligned.m8n8.x4.shared.b16 {%0,%1,%2,%3}, [%4];"
                 : "=r"(r0), "=r"(r1), "=r"(r2), "=r"(r3) : "r"(a));
}
__device__ __forceinline__ void ldsm4t(uint32_t& r0, uint32_t& r1,
                                       uint32_t& r2, uint32_t& r3, uint32_t a) {
    asm volatile("ldmatrix.sync.aligned.m8n8.x4.trans.shared.b16 {%0,%1,%2,%3}, [%4];"
                 : "=r"(r0), "=r"(r1), "=r"(r2), "=r"(r3) : "r"(a));
}
__device__ __forceinline__ void mma16816(float c[4], const uint32_t a[4],
                                         uint32_t b0, uint32_t b1) {
    asm volatile(
        "mma.sync.aligned.m16n8k16.row.col.f32.bf16.bf16.f32 "
        "{%0,%1,%2,%3}, {%4,%5,%6,%7}, {%8,%9}, {%0,%1,%2,%3};"
        : "+f"(c[0]), "+f"(c[1]), "+f"(c[2]), "+f"(c[3])
        : "r"(a[0]), "r"(a[1]), "r"(a[2]), "r"(a[3]), "r"(b0), "r"(b1));
}

// ---------------------------------------------------------------------------
// Universal bf16 tensor-core conv-as-GEMM.
//   Y[b,m,t] = bias[m] + sum_{ci,kw} W[m, ci*KW+kw] * Xpad[b, ci, t + kw]
// Xpad has row stride XS and is already halo-padded (halo = KW/2).
// Tile: TM=128 x TN=64 x TK=32; 8 warps as 4(m) x 2(n), 32x32 per warp.
// ---------------------------------------------------------------------------
template <int KW, bool RELU, typename OutT>
__global__ void __launch_bounds__(256) mma_conv_kernel(
    const bf16* __restrict__ W, const float* __restrict__ bias,
    const bf16* __restrict__ X, OutT* __restrict__ Y,
    int M, int T, int XS, int Cin)
{
    constexpr int TM = 128, TN = 64, TK = 32;
    constexpr int BSTR = 72;                   // bf16 units (144B rows)
    __shared__ bf16 As[TM * TK];               // row stride 32 (64B)
    __shared__ bf16 Bs[TK * BSTR];

    const int K  = Cin * KW;
    const int b  = blockIdx.z;
    const int m0 = blockIdx.y * TM;
    const int t0 = blockIdx.x * TN;
    const int tid = threadIdx.x, lane = tid & 31, wid = tid >> 5;
    const int wm = (wid >> 1) * 32;            // warp m offset in tile
    const int wn = (wid & 1) * 32;             // warp n offset in tile
    const bf16* Xb = X + (long)b * Cin * XS;

    float acc[2][4][4];
#pragma unroll
    for (int mi = 0; mi < 2; mi++)
#pragma unroll
        for (int j = 0; j < 4; j++)
#pragma unroll
            for (int c = 0; c < 4; c++) acc[mi][j][c] = 0.f;

    const uint32_t As_base = smem_u32(As);
    const uint32_t Bs_base = smem_u32(Bs);

    const int iters = (K + TK - 1) / TK;
    for (int it = 0; it < iters; it++) {
        const int k0 = it * TK;
        // ---- stage A: 128 rows x 32 bf16, 512 16B-chunks, 2 per thread ----
#pragma unroll
        for (int r = 0; r < 2; r++) {
            int cid = tid + 256 * r;
            int row = cid >> 2, ch = (cid & 3) * 8;
            int gm = m0 + row, gk = k0 + ch;
            uint4 v = make_uint4(0u, 0u, 0u, 0u);
            if (gm < M && gk < K) v = *(const uint4*)(W + (long)gm * K + gk);
            *(uint4*)(As + row * TK + ch) = v;
        }
        // ---- stage B: 32 rows x 64 bf16 (im2row with kw shift) ------------
        {
            int kk = tid >> 3, nseg = (tid & 7) * 8;
            int gk = k0 + kk;
            bf16 tmp[8];
            if (gk < K) {
                int ci, kw;
                if (KW == 1) { ci = gk; kw = 0; }
                else { ci = gk / KW; kw = gk - ci * KW; }
                const bf16* src = Xb + (long)ci * XS + t0 + nseg + kw;
#pragma unroll
                for (int j = 0; j < 8; j++) tmp[j] = src[j];
            } else {
#pragma unroll
                for (int j = 0; j < 8; j++) tmp[j] = __float2bfloat16(0.f);
            }
#pragma unroll
            for (int j = 0; j < 8; j++) Bs[kk * BSTR + nseg + j] = tmp[j];
        }
        __syncthreads();
        // ---- compute: 2 k16-steps, per warp 16 mma ------------------------
#pragma unroll
        for (int kk = 0; kk < 2; kk++) {
            uint32_t a[2][4];
#pragma unroll
            for (int mi = 0; mi < 2; mi++) {
                uint32_t addr = As_base +
                    ((wm + mi * 16 + (lane & 15)) * TK + kk * 16 + (lane >> 4) * 8) * 2;
                ldsm4(a[mi][0], a[mi][1], a[mi][2], a[mi][3], addr);
            }
            uint32_t bf[2][4];
#pragma unroll
            for (int nj = 0; nj < 2; nj++) {
                uint32_t addr = Bs_base +
                    ((kk * 16 + (lane & 15)) * BSTR + wn + nj * 16 + (lane >> 4) * 8) * 2;
                ldsm4t(bf[nj][0], bf[nj][1], bf[nj][2], bf[nj][3], addr);
            }
#pragma unroll
            for (int mi = 0; mi < 2; mi++)
#pragma unroll
                for (int nj = 0; nj < 2; nj++) {
                    mma16816(acc[mi][nj * 2 + 0], a[mi], bf[nj][0], bf[nj][1]);
                    mma16816(acc[mi][nj * 2 + 1], a[mi], bf[nj][2], bf[nj][3]);
                }
        }
        __syncthreads();
    }

    // ---- epilogue ---------------------------------------------------------
    const int g = lane >> 2, tig = lane & 3;
#pragma unroll
    for (int mi = 0; mi < 2; mi++) {
#pragma unroll
        for (int h = 0; h < 2; h++) {
            int gm = m0 + wm + mi * 16 + g + h * 8;
            if (gm >= M) continue;
            float bb = bias[gm];
            OutT* Yr = Y + ((long)b * M + gm) * T;
#pragma unroll
            for (int j = 0; j < 4; j++) {
                int t = t0 + wn + j * 8 + tig * 2;
                if (t >= T) continue;
                float v0 = acc[mi][j][h * 2 + 0] + bb;
                float v1 = acc[mi][j][h * 2 + 1] + bb;
                if (RELU) { v0 = fmaxf(v0, 0.f); v1 = fmaxf(v1, 0.f); }
                if constexpr (sizeof(OutT) == 4) {
                    *(float2*)((float*)Yr + t) = make_float2(v0, v1);
                } else {
                    *(__nv_bfloat162*)((bf16*)Yr + t) = __floats2bfloat162_rn(v0, v1);
                }
            }
        }
    }
}

// ---------------------------------------------------------------------------
// attention: out = log_softmax(-T*|q-k|^2) + log(prior+1e-8); !mask -> -inf.
// q^2 cancels in log_softmax -> s_j = T*(2 q.k_j - |k_j|^2).
// ---------------------------------------------------------------------------
__global__ void __launch_bounds__(256) attn_kernel(
    const float* __restrict__ prior, const void* __restrict__ maskraw,
    float* __restrict__ out)
{
    __shared__ bf16 ks[80 * 256];
    __shared__ float k2s[256];
    __shared__ float qs[8 * 80];

    const int b = blockIdx.y;
    const int tid = threadIdx.x;
    const int mode = g_maskmode;
    const float* keysb = g_keys + (long)b * 80 * 256;

    for (int idx = tid; idx < 80 * 256; idx += 256)
        ks[idx] = __float2bfloat16(keysb[idx]);
    __syncthreads();
    {
        int t = tid;
        float s = 0.f;
#pragma unroll 8
        for (int c = 0; c < 80; c++) {
            float v = __bfloat162float(ks[c * 256 + t]);
            s += v * v;
        }
        k2s[t] = s;
    }
    __syncthreads();

    const int wid = tid >> 5, lane = tid & 31;
    for (int it = 0; it < 5; it++) {
        int row = blockIdx.x * 40 + it * 8 + wid;
        for (int c = lane; c < 80; c += 32)
            qs[wid * 80 + c] = g_Q[((long)b * 80 + c) * 1000 + row];
        __syncwarp();

        float acc[8];
#pragma unroll
        for (int j = 0; j < 8; j++) acc[j] = 0.f;
#pragma unroll 4
        for (int c = 0; c < 80; c++) {
            float qv = qs[wid * 80 + c];
            uint4 kv = *(const uint4*)&ks[c * 256 + lane * 8];
            float2 f0 = __bfloat1622float2(*(__nv_bfloat162*)&kv.x);
            float2 f1 = __bfloat1622float2(*(__nv_bfloat162*)&kv.y);
            float2 f2 = __bfloat1622float2(*(__nv_bfloat162*)&kv.z);
            float2 f3 = __bfloat1622float2(*(__nv_bfloat162*)&kv.w);
            acc[0] += qv * f0.x; acc[1] += qv * f0.y;
            acc[2] += qv * f1.x; acc[3] += qv * f1.y;
            acc[4] += qv * f2.x; acc[5] += qv * f2.y;
            acc[6] += qv * f3.x; acc[7] += qv * f3.y;
        }

        float s[8];
        float mx = -1e30f;
#pragma unroll
        for (int j = 0; j < 8; j++) {
            s[j] = 0.0005f * (2.f * acc[j] - k2s[lane * 8 + j]);
            mx = fmaxf(mx, s[j]);
        }
#pragma unroll
        for (int o = 16; o > 0; o >>= 1) mx = fmaxf(mx, __shfl_xor_sync(0xffffffffu, mx, o));
        float sum = 0.f;
#pragma unroll
        for (int j = 0; j < 8; j++) sum += __expf(s[j] - mx);
#pragma unroll
        for (int o = 16; o > 0; o >>= 1) sum += __shfl_xor_sync(0xffffffffu, sum, o);
        float lse = mx + __logf(sum);

        long base = ((long)(b * 1000 + row)) * 256 + lane * 8;
        float4 p0 = *(const float4*)(prior + base);
        float4 p1 = *(const float4*)(prior + base + 4);
        const float NEG = __int_as_float(0xff800000);
        float o8[8];
        o8[0] = s[0] - lse + __logf(p0.x + 1e-8f);
        o8[1] = s[1] - lse + __logf(p0.y + 1e-8f);
        o8[2] = s[2] - lse + __logf(p0.z + 1e-8f);
        o8[3] = s[3] - lse + __logf(p0.w + 1e-8f);
        o8[4] = s[4] - lse + __logf(p1.x + 1e-8f);
        o8[5] = s[5] - lse + __logf(p1.y + 1e-8f);
        o8[6] = s[6] - lse + __logf(p1.z + 1e-8f);
        o8[7] = s[7] - lse + __logf(p1.w + 1e-8f);

        if (mode == 1) {
            const int* mp = (const int*)maskraw;
#pragma unroll
            for (int j = 0; j < 8; j++) if (mp[base + j] == 0) o8[j] = NEG;
        } else if (mode == 2) {
            const float* mp = (const float*)maskraw;
#pragma unroll
            for (int j = 0; j < 8; j++) if (mp[base + j] == 0.f) o8[j] = NEG;
        } else {
            const uchar* mp = (const uchar*)maskraw;
            uchar4 m0 = *(const uchar4*)(mp + base);
            uchar4 m1 = *(const uchar4*)(mp + base + 4);
            if (!m0.x) o8[0] = NEG; if (!m0.y) o8[1] = NEG;
            if (!m0.z) o8[2] = NEG; if (!m0.w) o8[3] = NEG;
            if (!m1.x) o8[4] = NEG; if (!m1.y) o8[5] = NEG;
            if (!m1.z) o8[6] = NEG; if (!m1.w) o8[7] = NEG;
        }

        *(float4*)(out + base)     = make_float4(o8[0], o8[1], o8[2], o8[3]);
        *(float4*)(out + base + 4) = make_float4(o8[4], o8[5], o8[6], o8[7]);
        __syncwarp();
    }
}

// ---------------------------------------------------------------------------
extern "C" void kernel_launch(void* const* d_in, const int* in_sizes, int n_in,
                              void* d_out, int out_size)
{
    const float* phonemes = (const float*)d_in[0];
    const float* audio    = (const float*)d_in[1];
    const uchar* mask     = (const uchar*)d_in[2];
    const float* prior    = (const float*)d_in[3];
    const float* kw1 = (const float*)d_in[4];
    const float* kb1 = (const float*)d_in[5];
    const float* kw2 = (const float*)d_in[6];
    const float* kb2 = (const float*)d_in[7];
    const float* qw1 = (const float*)d_in[8];
    const float* qb1 = (const float*)d_in[9];
    const float* qw2 = (const float*)d_in[10];
    const float* qb2 = (const float*)d_in[11];
    const float* qw3 = (const float*)d_in[12];
    const float* qb3 = (const float*)d_in[13];
    float* out = (float*)d_out;

    void* p;
    cudaGetSymbolAddress(&p, g_wk1);   bf16* wk1 = (bf16*)p;
    cudaGetSymbolAddress(&p, g_wq1);   bf16* wq1 = (bf16*)p;
    cudaGetSymbolAddress(&p, g_wk2);   bf16* wk2 = (bf16*)p;
    cudaGetSymbolAddress(&p, g_wq2);   bf16* wq2 = (bf16*)p;
    cudaGetSymbolAddress(&p, g_wq3);   bf16* wq3 = (bf16*)p;
    cudaGetSymbolAddress(&p, g_phon);  bf16* phon = (bf16*)p;
    cudaGetSymbolAddress(&p, g_audio); bf16* aud  = (bf16*)p;
    cudaGetSymbolAddress(&p, g_H1b);   bf16* H1 = (bf16*)p;
    cudaGetSymbolAddress(&p, g_H2b);   bf16* H2 = (bf16*)p;
    cudaGetSymbolAddress(&p, g_H3b);   bf16* H3 = (bf16*)p;
    cudaGetSymbolAddress(&p, g_keys);  float* keys = (float*)p;
    cudaGetSymbolAddress(&p, g_Q);     float* Q = (float*)p;

    detect_mask_kernel<<<1, 32>>>(mask);

    {   // conversions
        long totw = 1024L * 1536 + 160 * 240 + 80 * 1024 + 80 * 160 + 80 * 80;
        prep_weights_kernel<<<(int)((totw + 255) / 256), 256>>>(kw1, qw1, kw2, qw2, qw3);
        long toti = (long)NB * 512 * 264 + (long)NB * 80 * 1032;
        prep_inputs_kernel<<<(int)((toti + 255) / 256), 256>>>(phonemes, audio);
    }

    // kconv1: [8,512,256] -> relu -> H1 bf16 [8,1024,256]
    mma_conv_kernel<3, true, bf16><<<dim3(4, 8, NB), 256>>>(
        wk1, kb1, phon, H1, 1024, 256, 264, 512);
    // qconv1: [8,80,1000] -> relu -> H2 bf16 [8,160,1000]
    mma_conv_kernel<3, true, bf16><<<dim3(16, 2, NB), 256>>>(
        wq1, qb1, aud, H2, 160, 1000, 1032, 80);
    // kconv2 (1x1): H1 -> keys f32 [8,80,256]
    mma_conv_kernel<1, false, float><<<dim3(4, 1, NB), 256>>>(
        wk2, kb2, H1, keys, 80, 256, 256, 1024);
    // qconv2 (1x1) + relu: H2 -> H3 bf16 [8,80,1000]
    mma_conv_kernel<1, true, bf16><<<dim3(16, 1, NB), 256>>>(
        wq2, qb2, H2, H3, 80, 1000, 1000, 160);
    // qconv3 (1x1): H3 -> Q f32 [8,80,1000]
    mma_conv_kernel<1, false, float><<<dim3(16, 1, NB), 256>>>(
        wq3, qb3, H3, Q, 80, 1000, 1000, 80);

    // attention + log_softmax + prior + mask
    attn_kernel<<<dim3(25, 8), 256>>>(prior, mask, out);
}

// round 9
// speedup vs baseline: 3.5863x; 1.7960x over previous
#include <cuda_runtime.h>
#include <cuda_bf16.h>
#include <cstdint>

typedef unsigned char uchar;
typedef unsigned short ushort;
typedef __nv_bfloat16 bf16;

#define NB 8

// ---------------- device scratch ----------------
__device__ __align__(16) bf16 g_wk1[1024 * 1536];
__device__ __align__(16) bf16 g_wq1[160 * 240];
__device__ __align__(16) bf16 g_wk2[80 * 1024];
__device__ __align__(16) bf16 g_wq2[80 * 160];
__device__ __align__(16) bf16 g_wq3[80 * 80];
__device__ __align__(16) bf16 g_phon [NB * 512 * 272];     // halo-padded, XS=272
__device__ __align__(16) bf16 g_audio[NB * 80 * 1040];     // halo-padded, XS=1040
__device__ __align__(16) bf16 g_H1b[NB * 1024 * 256];
__device__ __align__(16) bf16 g_H2b[NB * 160 * 1000 + 64];
__device__ __align__(16) bf16 g_H3b[NB * 80 * 1000 + 64];
__device__ __align__(16) float g_keysP[4 * NB * 80 * 256]; // split-K partials
__device__ __align__(16) bf16  g_keysBf[NB * 80 * 256];
__device__ __align__(16) float g_Q[NB * 80 * 1000];
__device__ int g_maskmode;                                 // 0=u8, 1=i32, 2=f32

union U8 { uint4 v; ushort u[8]; };

// ---------------- fused prep: weights+inputs conversion, padding, mask detect
__global__ void prep_kernel(
    const float* __restrict__ kw1, const float* __restrict__ qw1,
    const float* __restrict__ kw2, const float* __restrict__ qw2,
    const float* __restrict__ qw3, const float* __restrict__ phon,
    const float* __restrict__ aud, const uchar* __restrict__ mask)
{
    if (blockIdx.x == 0 && threadIdx.x == 0) {
        const unsigned* d = (const unsigned*)mask;
        bool i32 = true, f32 = true;
        for (int i = 0; i < 256; i++) {
            unsigned v = d[i];
            if (v != 0u && v != 1u) i32 = false;
            if (v != 0u && v != 0x3F800000u) f32 = false;
        }
        g_maskmode = i32 ? 1 : (f32 ? 2 : 0);
    }
    long i = (long)blockIdx.x * 256 + threadIdx.x;
    const long N1 = 1024L * 1536, N2 = 160 * 240, N3 = 80 * 1024,
               N4 = 80 * 160, N5 = 80 * 80;
    const long NP = 8L * 512 * 272, NA = 8L * 80 * 1040;
    if (i < N1) { g_wk1[i] = __float2bfloat16(kw1[i]); return; } i -= N1;
    if (i < N2) { g_wq1[i] = __float2bfloat16(qw1[i]); return; } i -= N2;
    if (i < N3) { g_wk2[i] = __float2bfloat16(kw2[i]); return; } i -= N3;
    if (i < N4) { g_wq2[i] = __float2bfloat16(qw2[i]); return; } i -= N4;
    if (i < N5) { g_wq3[i] = __float2bfloat16(qw3[i]); return; } i -= N5;
    if (i < NP) {
        long r = i / 272; int x = (int)(i - r * 272);
        g_phon[i] = (x >= 1 && x <= 256) ? __float2bfloat16(phon[r * 256 + x - 1])
                                         : __float2bfloat16(0.f);
        return;
    } i -= NP;
    if (i < NA) {
        long r = i / 1040; int x = (int)(i - r * 1040);
        g_audio[i] = (x >= 1 && x <= 1000) ? __float2bfloat16(aud[r * 1000 + x - 1])
                                           : __float2bfloat16(0.f);
    }
}

// ---------------- split-K reduce for keys -> bf16 ----------------
__global__ void reduce_keys_kernel()
{
    const int N = NB * 80 * 256;
    int i = blockIdx.x * 256 + threadIdx.x;
    if (i < N) {
        float s = g_keysP[i] + g_keysP[N + i] + g_keysP[2 * N + i] + g_keysP[3 * N + i];
        g_keysBf[i] = __float2bfloat16(s);
    }
}

// ---------------- mma helpers ----------------
__device__ __forceinline__ uint32_t smem_u32(const void* p) {
    return (uint32_t)__cvta_generic_to_shared(p);
}
__device__ __forceinline__ void ldsm4(uint32_t& r0, uint32_t& r1,
                                      uint32_t& r2, uint32_t& r3, uint32_t a) {
    asm volatile("ldmatrix.sync.aligned.m8n8.x4.shared.b16 {%0,%1,%2,%3}, [%4];"
                 : "=r"(r0), "=r"(r1), "=r"(r2), "=r"(r3) : "r"(a));
}
__device__ __forceinline__ void ldsm4t(uint32_t& r0, uint32_t& r1,
                                       uint32_t& r2, uint32_t& r3, uint32_t a) {
    asm volatile("ldmatrix.sync.aligned.m8n8.x4.trans.shared.b16 {%0,%1,%2,%3}, [%4];"
                 : "=r"(r0), "=r"(r1), "=r"(r2), "=r"(r3) : "r"(a));
}
__device__ __forceinline__ void mma16816(float c[4], const uint32_t a[4],
                                         uint32_t b0, uint32_t b1) {
    asm volatile(
        "mma.sync.aligned.m16n8k16.row.col.f32.bf16.bf16.f32 "
        "{%0,%1,%2,%3}, {%4,%5,%6,%7}, {%8,%9}, {%0,%1,%2,%3};"
        : "+f"(c[0]), "+f"(c[1]), "+f"(c[2]), "+f"(c[3])
        : "r"(a[0]), "r"(a[1]), "r"(a[2]), "r"(a[3]), "r"(b0), "r"(b1));
}

template <int BSTR, int TN>
__device__ __forceinline__ void storeB3(ushort* Brow, int pbase, uint4 v) {
    U8 u; u.v = v;
#pragma unroll
    for (int kw = 0; kw < 3; kw++)
#pragma unroll
        for (int j = 0; j < 8; j++) {
            int t = pbase + j - kw;
            if (t >= 0 && t < TN) Brow[kw * BSTR + t] = u.u[j];
        }
}

// ---------------------------------------------------------------------------
// Pipelined bf16 tensor-core conv-as-GEMM (double-buffered, 1 sync/iter).
//   Y[b,m,t] = bias[m] + sum_{ci,kw} W[m, ci*KW+kw] * Xpad[b, ci, t+kw]
// KW=3: TK=48 (16 channels x 3), B staged via register-shift im2row.
// KW=1: TK=32, fully vectorized staging.
// SPLIT: blockIdx.y = K-split index (kLen per split); partial outputs,
//        bias only in split 0; deterministic (no atomics).
// ---------------------------------------------------------------------------
template <int KW, int TKC, int TN, int WMI, int WNJ, bool RELU, bool SPLIT, typename OutT>
__global__ void __launch_bounds__(256) mma_conv(
    const bf16* __restrict__ W, const float* __restrict__ bias,
    const bf16* __restrict__ X, OutT* __restrict__ Y,
    int M, int T, int XS, int Ktot, int kLen)
{
    constexpr int TM = 128;
    constexpr int TK = TKC * KW;
    constexpr int KSTEPS = TK / 16;
    constexpr int ASTR = TK + 8;
    constexpr int BSTR = TN + 8;
    constexpr int WARPSN = TN / (16 * WNJ);
    constexpr int ACH = (TM * TK) / 2048;   // uint4 chunks per thread (A)
    constexpr int AKCH = TK / 8;

    extern __shared__ __align__(16) bf16 dsm[];
    bf16* Asm = dsm;                        // 2 * TM * ASTR
    bf16* Bsm = dsm + 2 * TM * ASTR;        // 2 * TK * BSTR

    const int tid = threadIdx.x, lane = tid & 31, wid = tid >> 5;
    const int b  = blockIdx.z;
    const int m0 = SPLIT ? 0 : blockIdx.y * TM;
    const int kb = SPLIT ? blockIdx.y * kLen : 0;
    const int kLim = min(kb + kLen, Ktot);
    const int Cin = Ktot / KW;
    const int t0 = blockIdx.x * TN;
    const int wm = (wid / WARPSN) * (WMI * 16);
    const int wn = (wid % WARPSN) * (WNJ * 16);
    const bf16* Xb = X + (long)b * Cin * XS;

    const uint32_t AsU = smem_u32(Asm);
    const uint32_t BsU = smem_u32(Bsm);

    float acc[WMI][WNJ * 2][4];
#pragma unroll
    for (int mi = 0; mi < WMI; mi++)
#pragma unroll
        for (int jj = 0; jj < WNJ * 2; jj++)
#pragma unroll
            for (int c = 0; c < 4; c++) acc[mi][jj][c] = 0.f;

    const int iters = (kLen + TK - 1) / TK;

    uint4 aR[ACH];
    uint4 bR0, bR1;

    auto loadA = [&](int it) {
#pragma unroll
        for (int r = 0; r < ACH; r++) {
            int cid = tid + 256 * r;
            int row = cid / AKCH;
            int ch  = (cid % AKCH) * 8;
            int gm = m0 + row;
            int gk = kb + it * TK + ch;
            uint4 v = make_uint4(0u, 0u, 0u, 0u);
            if (gm < M && gk < kLim) v = *(const uint4*)(W + (long)gm * Ktot + gk);
            aR[r] = v;
        }
    };
    auto storeA = [&](int p) {
#pragma unroll
        for (int r = 0; r < ACH; r++) {
            int cid = tid + 256 * r;
            int row = cid / AKCH;
            int ch  = (cid % AKCH) * 8;
            *(uint4*)(Asm + p * TM * ASTR + row * ASTR + ch) = aR[r];
        }
    };
    auto loadB = [&](int it) {
        if constexpr (KW == 1) {
            int kk = tid >> 3, seg = tid & 7;
            int c = kb + it * TK + kk;
            uint4 v = make_uint4(0u, 0u, 0u, 0u);
            if (c < kLim) v = *(const uint4*)(Xb + (long)c * XS + t0 + seg * 8);
            bR0 = v;
        } else {
            int r = tid >> 4, seg = tid & 15;
            const bf16* rowp = Xb + (long)(it * TKC + r) * XS + t0;
            bR0 = *(const uint4*)(rowp + seg * 8);
            constexpr int CHB = (TN + 16) / 8;
            if (seg + 16 < CHB) bR1 = *(const uint4*)(rowp + (seg + 16) * 8);
        }
    };
    auto storeB = [&](int p) {
        if constexpr (KW == 1) {
            int kk = tid >> 3, seg = tid & 7;
            *(uint4*)(Bsm + p * TK * BSTR + kk * BSTR + seg * 8) = bR0;
        } else {
            int r = tid >> 4, seg = tid & 15;
            ushort* Brow = (ushort*)(Bsm + p * TK * BSTR + (r * 3) * BSTR);
            constexpr int CHB = (TN + 16) / 8;
            storeB3<BSTR, TN>(Brow, seg * 8, bR0);
            if (seg + 16 < CHB) storeB3<BSTR, TN>(Brow, (seg + 16) * 8, bR1);
        }
    };
    auto compute = [&](int p) {
#pragma unroll
        for (int ks = 0; ks < KSTEPS; ks++) {
            uint32_t a[WMI][4];
#pragma unroll
            for (int mi = 0; mi < WMI; mi++) {
                uint32_t addr = AsU + (uint32_t)(p * TM * ASTR +
                    (wm + mi * 16 + (lane & 15)) * ASTR + ks * 16 + (lane >> 4) * 8) * 2;
                ldsm4(a[mi][0], a[mi][1], a[mi][2], a[mi][3], addr);
            }
            uint32_t bb[WNJ][4];
#pragma unroll
            for (int nj = 0; nj < WNJ; nj++) {
                uint32_t addr = BsU + (uint32_t)(p * TK * BSTR +
                    (ks * 16 + (lane & 15)) * BSTR + wn + nj * 16 + (lane >> 4) * 8) * 2;
                ldsm4t(bb[nj][0], bb[nj][1], bb[nj][2], bb[nj][3], addr);
            }
#pragma unroll
            for (int mi = 0; mi < WMI; mi++)
#pragma unroll
                for (int nj = 0; nj < WNJ; nj++) {
                    mma16816(acc[mi][nj * 2 + 0], a[mi], bb[nj][0], bb[nj][1]);
                    mma16816(acc[mi][nj * 2 + 1], a[mi], bb[nj][2], bb[nj][3]);
                }
        }
    };

    loadA(0); loadB(0);
    storeA(0); storeB(0);
    __syncthreads();
    for (int it = 0; it < iters; it++) {
        int p = it & 1;
        if (it + 1 < iters) { loadA(it + 1); loadB(it + 1); }
        compute(p);
        if (it + 1 < iters) {
            storeA(1 - p); storeB(1 - p);
            __syncthreads();
        }
    }

    // epilogue
    const int g = lane >> 2, tig = lane & 3;
#pragma unroll
    for (int mi = 0; mi < WMI; mi++)
#pragma unroll
        for (int h = 0; h < 2; h++) {
            int gm = m0 + wm + mi * 16 + g + h * 8;
            if (gm >= M) continue;
            float bv = (!SPLIT || blockIdx.y == 0) ? bias[gm] : 0.f;
            OutT* Yr;
            if constexpr (SPLIT)
                Yr = Y + ((long)(blockIdx.y * gridDim.z + b) * M + gm) * T;
            else
                Yr = Y + ((long)b * M + gm) * T;
#pragma unroll
            for (int jj = 0; jj < WNJ * 2; jj++) {
                int t = t0 + wn + jj * 8 + tig * 2;
                if (t >= T) continue;
                float v0 = acc[mi][jj][h * 2 + 0] + bv;
                float v1 = acc[mi][jj][h * 2 + 1] + bv;
                if (RELU) { v0 = fmaxf(v0, 0.f); v1 = fmaxf(v1, 0.f); }
                if constexpr (sizeof(OutT) == 4)
                    *(float2*)((float*)Yr + t) = make_float2(v0, v1);
                else
                    *(__nv_bfloat162*)((bf16*)Yr + t) = __floats2bfloat162_rn(v0, v1);
            }
        }
}

// ---------------------------------------------------------------------------
// attention: out = log_softmax(-T*|q-k|^2) + log(prior+1e-8); !mask -> -inf.
// q^2 cancels in log_softmax -> s_j = T*(2 q.k_j - |k_j|^2).
// ---------------------------------------------------------------------------
__global__ void __launch_bounds__(256) attn_kernel(
    const float* __restrict__ prior, const void* __restrict__ maskraw,
    float* __restrict__ out)
{
    __shared__ __align__(16) bf16 ks[80 * 256];
    __shared__ float k2s[256];
    __shared__ float qs[8 * 80];

    const int b = blockIdx.y;
    const int tid = threadIdx.x;
    const int mode = g_maskmode;
    const bf16* keysb = g_keysBf + (long)b * 80 * 256;

    for (int i = tid; i < 80 * 256 / 8; i += 256)
        ((uint4*)ks)[i] = ((const uint4*)keysb)[i];
    __syncthreads();
    {
        int t = tid;
        float s = 0.f;
#pragma unroll 8
        for (int c = 0; c < 80; c++) {
            float v = __bfloat162float(ks[c * 256 + t]);
            s += v * v;
        }
        k2s[t] = s;
    }
    __syncthreads();

    const int wid = tid >> 5, lane = tid & 31;
    for (int it = 0; it < 5; it++) {
        int row = blockIdx.x * 40 + it * 8 + wid;
        for (int c = lane; c < 80; c += 32)
            qs[wid * 80 + c] = g_Q[((long)b * 80 + c) * 1000 + row];
        __syncwarp();

        float acc[8];
#pragma unroll
        for (int j = 0; j < 8; j++) acc[j] = 0.f;
#pragma unroll 4
        for (int c = 0; c < 80; c++) {
            float qv = qs[wid * 80 + c];
            uint4 kv = *(const uint4*)&ks[c * 256 + lane * 8];
            float2 f0 = __bfloat1622float2(*(__nv_bfloat162*)&kv.x);
            float2 f1 = __bfloat1622float2(*(__nv_bfloat162*)&kv.y);
            float2 f2 = __bfloat1622float2(*(__nv_bfloat162*)&kv.z);
            float2 f3 = __bfloat1622float2(*(__nv_bfloat162*)&kv.w);
            acc[0] += qv * f0.x; acc[1] += qv * f0.y;
            acc[2] += qv * f1.x; acc[3] += qv * f1.y;
            acc[4] += qv * f2.x; acc[5] += qv * f2.y;
            acc[6] += qv * f3.x; acc[7] += qv * f3.y;
        }

        float s[8];
        float mx = -1e30f;
#pragma unroll
        for (int j = 0; j < 8; j++) {
            s[j] = 0.0005f * (2.f * acc[j] - k2s[lane * 8 + j]);
            mx = fmaxf(mx, s[j]);
        }
#pragma unroll
        for (int o = 16; o > 0; o >>= 1) mx = fmaxf(mx, __shfl_xor_sync(0xffffffffu, mx, o));
        float sum = 0.f;
#pragma unroll
        for (int j = 0; j < 8; j++) sum += __expf(s[j] - mx);
#pragma unroll
        for (int o = 16; o > 0; o >>= 1) sum += __shfl_xor_sync(0xffffffffu, sum, o);
        float lse = mx + __logf(sum);

        long base = ((long)(b * 1000 + row)) * 256 + lane * 8;
        float4 p0 = *(const float4*)(prior + base);
        float4 p1 = *(const float4*)(prior + base + 4);
        const float NEG = __int_as_float(0xff800000);
        float o8[8];
        o8[0] = s[0] - lse + __logf(p0.x + 1e-8f);
        o8[1] = s[1] - lse + __logf(p0.y + 1e-8f);
        o8[2] = s[2] - lse + __logf(p0.z + 1e-8f);
        o8[3] = s[3] - lse + __logf(p0.w + 1e-8f);
        o8[4] = s[4] - lse + __logf(p1.x + 1e-8f);
        o8[5] = s[5] - lse + __logf(p1.y + 1e-8f);
        o8[6] = s[6] - lse + __logf(p1.z + 1e-8f);
        o8[7] = s[7] - lse + __logf(p1.w + 1e-8f);

        if (mode == 1) {
            const int* mp = (const int*)maskraw;
#pragma unroll
            for (int j = 0; j < 8; j++) if (mp[base + j] == 0) o8[j] = NEG;
        } else if (mode == 2) {
            const float* mp = (const float*)maskraw;
#pragma unroll
            for (int j = 0; j < 8; j++) if (mp[base + j] == 0.f) o8[j] = NEG;
        } else {
            const uchar* mp = (const uchar*)maskraw;
            uchar4 m0 = *(const uchar4*)(mp + base);
            uchar4 m1 = *(const uchar4*)(mp + base + 4);
            if (!m0.x) o8[0] = NEG; if (!m0.y) o8[1] = NEG;
            if (!m0.z) o8[2] = NEG; if (!m0.w) o8[3] = NEG;
            if (!m1.x) o8[4] = NEG; if (!m1.y) o8[5] = NEG;
            if (!m1.z) o8[6] = NEG; if (!m1.w) o8[7] = NEG;
        }

        *(float4*)(out + base)     = make_float4(o8[0], o8[1], o8[2], o8[3]);
        *(float4*)(out + base + 4) = make_float4(o8[4], o8[5], o8[6], o8[7]);
        __syncwarp();
    }
}

// ---------------------------------------------------------------------------
extern "C" void kernel_launch(void* const* d_in, const int* in_sizes, int n_in,
                              void* d_out, int out_size)
{
    const float* phonemes = (const float*)d_in[0];
    const float* audio    = (const float*)d_in[1];
    const uchar* mask     = (const uchar*)d_in[2];
    const float* prior    = (const float*)d_in[3];
    const float* kw1 = (const float*)d_in[4];
    const float* kb1 = (const float*)d_in[5];
    const float* kw2 = (const float*)d_in[6];
    const float* kb2 = (const float*)d_in[7];
    const float* qw1 = (const float*)d_in[8];
    const float* qb1 = (const float*)d_in[9];
    const float* qw2 = (const float*)d_in[10];
    const float* qb2 = (const float*)d_in[11];
    const float* qw3 = (const float*)d_in[12];
    const float* qb3 = (const float*)d_in[13];
    float* out = (float*)d_out;

    void* p;
    cudaGetSymbolAddress(&p, g_wk1);    bf16* wk1 = (bf16*)p;
    cudaGetSymbolAddress(&p, g_wq1);    bf16* wq1 = (bf16*)p;
    cudaGetSymbolAddress(&p, g_wk2);    bf16* wk2 = (bf16*)p;
    cudaGetSymbolAddress(&p, g_wq2);    bf16* wq2 = (bf16*)p;
    cudaGetSymbolAddress(&p, g_wq3);    bf16* wq3 = (bf16*)p;
    cudaGetSymbolAddress(&p, g_phon);   bf16* phon = (bf16*)p;
    cudaGetSymbolAddress(&p, g_audio);  bf16* aud  = (bf16*)p;
    cudaGetSymbolAddress(&p, g_H1b);    bf16* H1 = (bf16*)p;
    cudaGetSymbolAddress(&p, g_H2b);    bf16* H2 = (bf16*)p;
    cudaGetSymbolAddress(&p, g_H3b);    bf16* H3 = (bf16*)p;
    cudaGetSymbolAddress(&p, g_keysP);  float* keysP = (float*)p;
    cudaGetSymbolAddress(&p, g_Q);      float* Q = (float*)p;

    // smem sizes (mirror of kernel constexprs)
    const int SMEM_K3 = (2 * 128 * 56 + 2 * 48 * 136) * 2;  // 54784
    const int SMEM_K1 = (2 * 128 * 40 + 2 * 32 * 72) * 2;   // 29696

    cudaFuncSetAttribute(mma_conv<3, 16, 128, 4, 2, true, false, bf16>,
                         cudaFuncAttributeMaxDynamicSharedMemorySize, SMEM_K3);

    // prep: total elements = weights + padded inputs
    {
        long total = 1024L * 1536 + 160 * 240 + 80 * 1024 + 80 * 160 + 80 * 80
                   + 8L * 512 * 272 + 8L * 80 * 1040;
        prep_kernel<<<(int)((total + 255) / 256), 256>>>(
            kw1, qw1, kw2, qw2, qw3, phonemes, audio, mask);
    }

    // kconv1: [8,512,256] -> relu -> H1 bf16 [8,1024,256]
    mma_conv<3, 16, 128, 4, 2, true, false, bf16>
        <<<dim3(2, 8, NB), 256, SMEM_K3>>>(wk1, kb1, phon, H1, 1024, 256, 272, 1536, 1536);
    // qconv1: [8,80,1000] -> relu -> H2 bf16 [8,160,1000]
    mma_conv<3, 16, 128, 4, 2, true, false, bf16>
        <<<dim3(8, 2, NB), 256, SMEM_K3>>>(wq1, qb1, aud, H2, 160, 1000, 1040, 240, 240);
    // kconv2 (1x1, split-K x4): H1 -> keysP partials
    mma_conv<1, 32, 64, 2, 2, false, true, float>
        <<<dim3(4, 4, NB), 256, SMEM_K1>>>(wk2, kb2, H1, keysP, 80, 256, 256, 1024, 256);
    reduce_keys_kernel<<<(NB * 80 * 256 + 255) / 256, 256>>>();
    // qconv2 (1x1) + relu: H2 -> H3 bf16
    mma_conv<1, 32, 64, 2, 2, true, false, bf16>
        <<<dim3(16, 1, NB), 256, SMEM_K1>>>(wq2, qb2, H2, H3, 80, 1000, 1000, 160, 160);
    // qconv3 (1x1): H3 -> Q f32
    mma_conv<1, 32, 64, 2, 2, false, false, float>
        <<<dim3(16, 1, NB), 256, SMEM_K1>>>(wq3, qb3, H3, Q, 80, 1000, 1000, 80, 80);

    // attention + log_softmax + prior + mask
    attn_kernel<<<dim3(25, 8), 256>>>(prior, mask, out);
}